// round 5
// baseline (speedup 1.0000x reference)
#include <cuda_runtime.h>
#include <cstdint>

// Problem constants
#define NCH      64          // input channels (= K per shift)
#define NOUT     64          // output channels
#define BAND_PX  200         // padded band length in pixels (198 used)
#define BAND_USED 198
#define BPAD     72          // padded N-stride of B slice in smem (conflict-free: 72%32=8)
#define PADW     34          // padded image width (32 + 2 reflect cols)
#define PADPIX   1156        // 34*34 padded pixels
#define LASTPIX  1155

// smem layout (floats):
//  band[64*200] | S1[200] | S2[200] | Bs[2][64*72] | wpart[4*64] | wsum[64]
#define SMEM_FLOATS (NCH*BAND_PX + 2*BAND_PX + 2*NCH*BPAD + 4*NOUT + NOUT)
#define SMEM_BYTES  (SMEM_FLOATS * 4)

__device__ __forceinline__ float tf32r(float x) {
    float r;
    asm("cvt.rna.tf32.f32 %0, %1;" : "=f"(r) : "f"(x));
    return r;
}

__device__ __forceinline__ void mma8(float* d, const uint32_t* A, const uint32_t* B) {
    asm volatile(
        "mma.sync.aligned.m16n8k8.row.col.f32.tf32.tf32.f32 "
        "{%0,%1,%2,%3}, {%4,%5,%6,%7}, {%8,%9}, {%0,%1,%2,%3};\n"
        : "+f"(d[0]), "+f"(d[1]), "+f"(d[2]), "+f"(d[3])
        : "r"(A[0]), "r"(A[1]), "r"(A[2]), "r"(A[3]), "r"(B[0]), "r"(B[1]));
}

__global__ __launch_bounds__(256, 2)
void norm_conv_kernel(const float* __restrict__ a,
                      const float* __restrict__ W,
                      float* __restrict__ out)
{
    extern __shared__ float smem[];
    float* band  = smem;                      // 64*200
    float* S1    = band + NCH * BAND_PX;      // 200
    float* S2    = S1 + BAND_PX;              // 200
    float* Bs    = S2 + BAND_PX;              // 2*64*72
    float* wpart = Bs + 2 * NCH * BPAD;       // 4*64
    float* wsum  = wpart + 4 * NOUT;          // 64

    const int tid    = threadIdx.x;
    const int b      = blockIdx.y;            // batch
    const int t      = blockIdx.x;            // pixel tile 0..8
    const int pstart = 128 * t;               // first band pixel (padded coords)
    const int p0     = pstart + 35;           // first output pixel of this tile

    const float* abase = a + (size_t)b * NCH * 1024;

    // ---- 1) Load reflect-padded linear band into smem (tf32-rounded) ----
    for (int j = tid; j < NCH * BAND_PX; j += 256) {
        int c  = j / BAND_PX;
        int pp = j - c * BAND_PX;
        int pPad = pstart + pp;
        pPad = min(pPad, LASTPIX);
        int row = pPad / PADW;
        int col = pPad - row * PADW;
        int y = row - 1; y = (y < 0) ? 1 : ((y > 31) ? 30 : y);
        int x = col - 1; x = (x < 0) ? 1 : ((x > 31) ? 30 : x);
        band[c * BAND_PX + pp] = tf32r(abase[c * 1024 + y * 32 + x]);
    }

    // ---- 2) W column-sum partials (S[o] = sum_p W[p][o]) ----
    {
        int o = tid & 63;
        int q = tid >> 6;
        float s = 0.f;
        int pe = (q + 1) * 144;
        for (int p = q * 144; p < pe; ++p)
            s += W[p * 64 + o];
        wpart[q * 64 + o] = s;
    }

    // ---- 3) Prefetch B slice for shift 0 into registers ----
    float4 pf[4];
    {
        int seg = tid & 15;
        int cb  = tid >> 4;
        #pragma unroll
        for (int i = 0; i < 4; ++i) {
            int c = cb + 16 * i;
            pf[i] = *reinterpret_cast<const float4*>(W + (c * 9 + 0) * 64 + seg * 4);
        }
    }

    __syncthreads();

    // ---- 4) Per-pixel channel sums (S1/S2), store B slice 0, reduce wsum ----
    for (int pp = tid; pp < BAND_USED; pp += 256) {
        float s1 = 0.f, s2 = 0.f;
        #pragma unroll 8
        for (int c = 0; c < NCH; ++c) {
            float v = band[c * BAND_PX + pp];
            s1 += v;
            s2 += v * v;
        }
        S1[pp] = s1;
        S2[pp] = s2;
    }
    {
        int seg = tid & 15;
        int cb  = tid >> 4;
        #pragma unroll
        for (int i = 0; i < 4; ++i) {
            int c = cb + 16 * i;
            float* dst = Bs + c * BPAD + seg * 4;
            dst[0] = tf32r(pf[i].x);
            dst[1] = tf32r(pf[i].y);
            dst[2] = tf32r(pf[i].z);
            dst[3] = tf32r(pf[i].w);
        }
    }
    if (tid < 64)
        wsum[tid] = wpart[tid] + wpart[64 + tid] + wpart[128 + tid] + wpart[192 + tid];

    __syncthreads();

    // ---- 5) Main MMA loop: 9 shifts x 8 k8-steps ----
    const int warp = tid >> 5;
    const int lane = tid & 31;
    const int gid  = lane >> 2;   // 0..7
    const int tig  = lane & 3;    // 0..3
    const int wm   = warp & 3;    // M-warp 0..3 (32 pixels each)
    const int wn   = warp >> 2;   // N-warp 0..1 (32 och each)

    float acc[2][4][4];
    #pragma unroll
    for (int mt = 0; mt < 2; ++mt)
        #pragma unroll
        for (int nt = 0; nt < 4; ++nt)
            #pragma unroll
            for (int r = 0; r < 4; ++r)
                acc[mt][nt][r] = 0.f;

    const uint32_t* bb = reinterpret_cast<const uint32_t*>(band);

    for (int s = 0; s < 9; ++s) {
        // prefetch next W slice (LDG overlaps MMA below)
        if (s < 8) {
            int seg = tid & 15;
            int cb  = tid >> 4;
            #pragma unroll
            for (int i = 0; i < 4; ++i) {
                int c = cb + 16 * i;
                pf[i] = *reinterpret_cast<const float4*>(W + (c * 9 + s + 1) * 64 + seg * 4);
            }
        }

        const uint32_t* bsu = reinterpret_cast<const uint32_t*>(Bs + (s & 1) * NCH * BPAD);
        int kh = s / 3;
        int kw = s - kh * 3;
        int delta = (kh - 1) * PADW + (kw - 1);
        int qa = 35 + wm * 32 + delta + gid;   // band pixel for A row 'gid'

        #pragma unroll
        for (int c0 = 0; c0 < NCH; c0 += 8) {
            uint32_t Af[2][4];
            int abase0 = (c0 + tig) * BAND_PX + qa;
            #pragma unroll
            for (int mt = 0; mt < 2; ++mt) {
                int ab = abase0 + mt * 16;
                Af[mt][0] = bb[ab];
                Af[mt][1] = bb[ab + 8];
                Af[mt][2] = bb[ab + 4 * BAND_PX];
                Af[mt][3] = bb[ab + 4 * BAND_PX + 8];
            }
            int bbase = (c0 + tig) * BPAD + wn * 32 + gid;
            #pragma unroll
            for (int nt = 0; nt < 4; ++nt) {
                uint32_t Bf[2];
                Bf[0] = bsu[bbase + nt * 8];
                Bf[1] = bsu[bbase + nt * 8 + 4 * BPAD];
                #pragma unroll
                for (int mt = 0; mt < 2; ++mt)
                    mma8(acc[mt][nt], Af[mt], Bf);
            }
        }

        if (s < 8) {
            __syncthreads();   // all warps done reading buffer (s+1)&1
            int seg = tid & 15;
            int cb  = tid >> 4;
            float* dstbuf = Bs + ((s + 1) & 1) * NCH * BPAD;
            #pragma unroll
            for (int i = 0; i < 4; ++i) {
                int c = cb + 16 * i;
                float* dst = dstbuf + c * BPAD + seg * 4;
                dst[0] = tf32r(pf[i].x);
                dst[1] = tf32r(pf[i].y);
                dst[2] = tf32r(pf[i].z);
                dst[3] = tf32r(pf[i].w);
            }
            __syncthreads();
        }
    }

    // ---- 6) Epilogue: out = (raw - mean * wsum[o]) / std ----
    #pragma unroll
    for (int mt = 0; mt < 2; ++mt) {
        #pragma unroll
        for (int half = 0; half < 2; ++half) {
            int q = 35 + wm * 32 + mt * 16 + gid + half * 8;  // band index of this pixel
            float psum = 0.f, psq = 0.f;
            #pragma unroll
            for (int dr = -1; dr <= 1; ++dr)
                #pragma unroll
                for (int dc = -1; dc <= 1; ++dc) {
                    int qq = q + dr * PADW + dc;
                    psum += S1[qq];
                    psq  += S2[qq];
                }
            float mean = psum * (1.0f / 576.0f);
            float var  = (psq - psum * psum * (1.0f / 576.0f)) * (1.0f / 575.0f);
            float rstd = rsqrtf(var);

            int p   = p0 + wm * 32 + mt * 16 + gid + half * 8;
            int row = p / PADW;
            int col = p - row * PADW;
            bool valid = (col >= 1) && (col <= 32) && (row >= 1) && (row <= 32);
            if (valid) {
                int y = row - 1, x = col - 1;
                float* obase = out + (size_t)b * NOUT * 1024 + y * 32 + x;
                #pragma unroll
                for (int nt = 0; nt < 4; ++nt) {
                    int o = wn * 32 + nt * 8 + tig * 2;
                    float v0 = (acc[mt][nt][half * 2 + 0] - mean * wsum[o])     * rstd;
                    float v1 = (acc[mt][nt][half * 2 + 1] - mean * wsum[o + 1]) * rstd;
                    obase[(size_t)o * 1024]       = v0;
                    obase[(size_t)(o + 1) * 1024] = v1;
                }
            }
        }
    }
}

extern "C" void kernel_launch(void* const* d_in, const int* in_sizes, int n_in,
                              void* d_out, int out_size)
{
    const float* a = (const float*)d_in[0];     // [256,64,32,32]
    const float* W = (const float*)d_in[1];     // [576,64]
    float* out = (float*)d_out;                 // [256,64,32,32]

    cudaFuncSetAttribute(norm_conv_kernel,
                         cudaFuncAttributeMaxDynamicSharedMemorySize, SMEM_BYTES);

    dim3 grid(9, 256);   // 9 pixel tiles x 256 batches
    norm_conv_kernel<<<grid, 256, SMEM_BYTES>>>(a, W, out);
}